// round 10
// baseline (speedup 1.0000x reference)
#include <cuda_runtime.h>
#include <cuda_bf16.h>

// Problem constants (fixed by the dataset)
#define Bsz   32768
#define INF   784
#define Hdim  128
#define OUTD  10
#define NSTEP 25

typedef unsigned long long u64;

// -------- packed f32x2 helpers (Blackwell dual-fp32 pipe) --------
__device__ __forceinline__ u64 fma2(u64 a, u64 b, u64 c) {
    u64 d;
    asm("fma.rn.f32x2 %0, %1, %2, %3;" : "=l"(d) : "l"(a), "l"(b), "l"(c));
    return d;
}
__device__ __forceinline__ u64 pack2(float x, float y) {
    u64 d;
    asm("mov.b64 %0, {%1, %2};" : "=l"(d) : "f"(x), "f"(y));
    return d;
}
__device__ __forceinline__ float2 unpack2(u64 a) {
    float2 r;
    asm("mov.b64 {%0, %1}, %2;" : "=f"(r.x), "=f"(r.y) : "l"(a));
    return r;
}

// -------- device scratch (no allocation allowed) --------
__device__ float g_cur1[(size_t)Bsz * Hdim];   // 16 MB
__device__ float g_W1T[(size_t)INF * Hdim];    // 400 KB, W1 transposed [k][h]
__device__ u64   g_W2p[Hdim * 6];              // per-h packed (o,o+1) weight pairs

// ============================================================
// prep: transpose W1, pack W2 pairs
// ============================================================
__global__ void prep_kernel(const float* __restrict__ W1, const float* __restrict__ W2) {
    int idx = blockIdx.x * 256 + threadIdx.x;
    if (idx < INF * Hdim) {
        int k = idx >> 7;        // /128
        int h = idx & 127;
        g_W1T[idx] = W1[h * INF + k];
    }
    if (idx < Hdim) {
        int h = idx;
#pragma unroll
        for (int p = 0; p < 5; p++) {
            g_W2p[h * 6 + p] = pack2(W2[(2 * p) * Hdim + h], W2[(2 * p + 1) * Hdim + h]);
        }
        g_W2p[h * 6 + 5] = 0ull;
    }
}

// ============================================================
// gemm1: cur1[b][h] = sum_k x[b][k] * W1[h][k] + b1[h]
// Tile 128x128, BK=16, 256 threads, 8x8 microtile.
// Accumulators packed over COLUMN pairs -> B operand loads directly as
// float2 (no dup MOVs); A tile stored pre-duplicated (a,a) in smem.
// Strided column mapping (2*tx + 32*j) -> conflict-free 1-phase LDS.
// Inner loop: 12 LDS.64 + 32 FFMA2, nothing else.
// Reduction order: single accumulator per scalar element, ascending-k FMA
// chain; bias added once after full-K reduction (bitwise rel_err 0.0 model).
// ============================================================
__global__ __launch_bounds__(256) void gemm1_kernel(const float* __restrict__ x,
                                                    const float* __restrict__ b1) {
    __shared__ float2 Asd[16][128];   // [k][row] duplicated (a,a)  - 16 KB
    __shared__ float  Bs[16][128];    // [k][col]                   - 8 KB
    __shared__ float  b1s[128];

    const int tid = threadIdx.x;
    const int bm = blockIdx.x * 128;

    if (tid < 128) b1s[tid] = b1[tid];

    // global load mapping
    const int arow = tid >> 2;          // 0..63
    const int acg  = (tid & 3) * 4;     // k sub-offset 0,4,8,12
    const int bk   = tid >> 5;          // 0..7
    const int bn   = (tid & 31) * 4;    // col 0..124

    const int tx = tid & 15;            // col group (strided cols 2tx+32j)
    const int ty = tid >> 4;            // row group (rows ty*8 .. ty*8+7)

    // accumulators: 8 rows x 4 column-pairs (cols 2tx+32j, +1)
    u64 cp[8][4];
#pragma unroll
    for (int ri = 0; ri < 8; ri++)
#pragma unroll
        for (int j = 0; j < 4; j++) cp[ri][j] = 0ull;

    // prefetch tile 0
    float4 a0 = *(const float4*)(x + (size_t)(bm + arow) * INF + acg);
    float4 a1 = *(const float4*)(x + (size_t)(bm + arow + 64) * INF + acg);
    float4 b0 = *(const float4*)(g_W1T + (size_t)bk * Hdim + bn);
    float4 b1v = *(const float4*)(g_W1T + (size_t)(bk + 8) * Hdim + bn);

    const int KITER = INF / 16;  // 49
    for (int t = 0; t < KITER; t++) {
        __syncthreads();
        // stage into smem (A duplicated)
        Asd[acg + 0][arow] = make_float2(a0.x, a0.x);
        Asd[acg + 1][arow] = make_float2(a0.y, a0.y);
        Asd[acg + 2][arow] = make_float2(a0.z, a0.z);
        Asd[acg + 3][arow] = make_float2(a0.w, a0.w);
        Asd[acg + 0][arow + 64] = make_float2(a1.x, a1.x);
        Asd[acg + 1][arow + 64] = make_float2(a1.y, a1.y);
        Asd[acg + 2][arow + 64] = make_float2(a1.z, a1.z);
        Asd[acg + 3][arow + 64] = make_float2(a1.w, a1.w);
        *(float4*)&Bs[bk][bn] = b0;
        *(float4*)&Bs[bk + 8][bn] = b1v;
        __syncthreads();

        if (t < KITER - 1) {
            int k0 = (t + 1) * 16;
            a0 = *(const float4*)(x + (size_t)(bm + arow) * INF + k0 + acg);
            a1 = *(const float4*)(x + (size_t)(bm + arow + 64) * INF + k0 + acg);
            b0 = *(const float4*)(g_W1T + (size_t)(k0 + bk) * Hdim + bn);
            b1v = *(const float4*)(g_W1T + (size_t)(k0 + bk + 8) * Hdim + bn);
        }

#pragma unroll
        for (int kk = 0; kk < 16; kk++) {
            u64 ap[8];
#pragma unroll
            for (int ri = 0; ri < 8; ri++)
                ap[ri] = *(const u64*)&Asd[kk][ty * 8 + ri];   // broadcast (a,a)
            u64 bp[4];
#pragma unroll
            for (int j = 0; j < 4; j++)
                bp[j] = *(const u64*)&Bs[kk][2 * tx + 32 * j]; // coalesced pair
#pragma unroll
            for (int ri = 0; ri < 8; ri++)
#pragma unroll
                for (int j = 0; j < 4; j++)
                    cp[ri][j] = fma2(ap[ri], bp[j], cp[ri][j]);
        }
    }

    // epilogue: add b1 (AFTER the full-K reduction), store float2 pairs
#pragma unroll
    for (int ri = 0; ri < 8; ri++) {
        int r = bm + ty * 8 + ri;
        float* orow = g_cur1 + (size_t)r * Hdim;
#pragma unroll
        for (int j = 0; j < 4; j++) {
            int c = 2 * tx + 32 * j;
            float2 v = unpack2(cp[ri][j]);
            float2 s;
            s.x = __fadd_rn(v.x, b1s[c]);
            s.y = __fadd_rn(v.y, b1s[c + 1]);
            *(float2*)&orow[c] = s;
        }
    }
}

// ============================================================
// snn: fused 25-step LIF + tiny GEMM. One thread = one batch row.
// m1[128] in REGISTERS (no launch-bounds cap -> no spill; at <=2 warps/SMSP
// the regfile never limits occupancy). cur1 tile + packed W2 in smem.
// 128 threads/CTA, grid 256, 2 CTAs/SM (smem 72.3 KB each).
// Arithmetic bitwise identical to the rel_err==0.0 version:
//   mem = fma(BETA, mem_prev, cur); mem -= (mem_prev > 1);  (FFMA + sel-add)
//   cur2 = ascending-h FFMA chain, +b2 after the reduction.
// ============================================================
#define SNN_THREADS 128
#define SNN_CUR1_OFF 0
#define SNN_W2_OFF   (128 * 129 * 4)              // 66048
#define SNN_B2_OFF   (SNN_W2_OFF + Hdim * 6 * 8)  // 72192
#define SNN_SMEM_BYTES (SNN_B2_OFF + 64)

__global__ __launch_bounds__(SNN_THREADS) void snn_kernel(const float* __restrict__ b2g,
                                                          float* __restrict__ out) {
    extern __shared__ char smem[];
    float (*cur1s)[129] = (float (*)[129])(smem + SNN_CUR1_OFF);  // stride 129: conflict-free
    u64*   w2s          = (u64*)(smem + SNN_W2_OFF);
    float* b2s          = (float*)(smem + SNN_B2_OFF);

    const int tid = threadIdx.x;
    const int rbase = blockIdx.x * SNN_THREADS;

    // load cur1 tile (vector LDG, scalar STS due to pad)
    for (int i = tid; i < SNN_THREADS * 32; i += SNN_THREADS) {
        int r = i >> 5;
        int c4 = (i & 31) * 4;
        float4 v = *(const float4*)&g_cur1[(size_t)(rbase + r) * Hdim + c4];
        cur1s[r][c4 + 0] = v.x; cur1s[r][c4 + 1] = v.y;
        cur1s[r][c4 + 2] = v.z; cur1s[r][c4 + 3] = v.w;
    }
    for (int i = tid; i < Hdim * 6; i += SNN_THREADS) w2s[i] = g_W2p[i];
    if (tid < OUTD) b2s[tid] = b2g[tid];
    __syncthreads();

    float m1[Hdim];
#pragma unroll
    for (int h = 0; h < Hdim; h++) m1[h] = 0.0f;
    float m2[OUTD];
#pragma unroll
    for (int o = 0; o < OUTD; o++) m2[o] = 0.0f;

    const int row = rbase + tid;
    const float* myc = cur1s[tid];
    float* outp = out + (size_t)row * OUTD;

    const u64 ONE2 = 0x3F8000003F800000ull;  // packed (1.0f, 1.0f)

#pragma unroll 1
    for (int t = 0; t < NSTEP; t++) {
        u64 acc0 = 0ull, acc1 = 0ull, acc2 = 0ull, acc3 = 0ull, acc4 = 0ull;
#pragma unroll
        for (int h = 0; h < Hdim; h++) {
            float mo = m1[h];
            // mem = fma(beta, mem, cur1) - r*THR  (XLA's contraction of the reference)
            float m = __fmaf_rn(0.9f, mo, myc[h]);
            if (mo > 1.0f) m = __fadd_rn(m, -1.0f);
            m1[h] = m;
            u64 sp = (m > 1.0f) ? ONE2 : 0ull;   // packed spike (s,s)
            const u64* w = &w2s[h * 6];
            acc0 = fma2(sp, w[0], acc0);
            acc1 = fma2(sp, w[1], acc1);
            acc2 = fma2(sp, w[2], acc2);
            acc3 = fma2(sp, w[3], acc3);
            acc4 = fma2(sp, w[4], acc4);
        }
        float c2[OUTD];
        {
            float2 v;
            v = unpack2(acc0); c2[0] = v.x; c2[1] = v.y;
            v = unpack2(acc1); c2[2] = v.x; c2[3] = v.y;
            v = unpack2(acc2); c2[4] = v.x; c2[5] = v.y;
            v = unpack2(acc3); c2[6] = v.x; c2[7] = v.y;
            v = unpack2(acc4); c2[8] = v.x; c2[9] = v.y;
        }
        float so[OUTD];
#pragma unroll
        for (int o = 0; o < OUTD; o++) {
            float cu = __fadd_rn(c2[o], b2s[o]);        // + b2 after the reduction
            float mo = m2[o];
            float m = __fmaf_rn(0.9f, mo, cu);          // one rounding (FFMA)
            if (mo > 1.0f) m = __fadd_rn(m, -1.0f);
            m2[o] = m;
            so[o] = (m > 1.0f) ? 1.0f : 0.0f;
        }
        float* op = outp + (size_t)t * Bsz * OUTD;
#pragma unroll
        for (int p = 0; p < 5; p++)
            *(float2*)(op + 2 * p) = make_float2(so[2 * p], so[2 * p + 1]);
    }
}

// ============================================================
extern "C" void kernel_launch(void* const* d_in, const int* in_sizes, int n_in,
                              void* d_out, int out_size) {
    (void)in_sizes; (void)n_in; (void)out_size;
    const float* x  = (const float*)d_in[0];
    const float* W1 = (const float*)d_in[1];
    const float* b1 = (const float*)d_in[2];
    const float* W2 = (const float*)d_in[3];
    const float* b2 = (const float*)d_in[4];
    float* out = (float*)d_out;

    static bool attr_set = false;
    if (!attr_set) {
        cudaFuncSetAttribute(snn_kernel, cudaFuncAttributeMaxDynamicSharedMemorySize,
                             SNN_SMEM_BYTES);
        attr_set = true;
    }

    prep_kernel<<<(INF * Hdim + 255) / 256, 256>>>(W1, W2);
    gemm1_kernel<<<Bsz / 128, 256>>>(x, b1);
    snn_kernel<<<Bsz / SNN_THREADS, SNN_THREADS, SNN_SMEM_BYTES>>>(b2, out);
}

// round 11
// speedup vs baseline: 3.2005x; 3.2005x over previous
#include <cuda_runtime.h>
#include <cuda_bf16.h>

// Problem constants (fixed by the dataset)
#define Bsz   32768
#define INF   784
#define Hdim  128
#define OUTD  10
#define NSTEP 25

typedef unsigned long long u64;

// -------- packed f32x2 helpers (Blackwell dual-fp32 pipe) --------
__device__ __forceinline__ u64 fma2(u64 a, u64 b, u64 c) {
    u64 d;
    asm("fma.rn.f32x2 %0, %1, %2, %3;" : "=l"(d) : "l"(a), "l"(b), "l"(c));
    return d;
}
__device__ __forceinline__ u64 pack2(float x, float y) {
    u64 d;
    asm("mov.b64 %0, {%1, %2};" : "=l"(d) : "f"(x), "f"(y));
    return d;
}
__device__ __forceinline__ float2 unpack2(u64 a) {
    float2 r;
    asm("mov.b64 {%0, %1}, %2;" : "=f"(r.x), "=f"(r.y) : "l"(a));
    return r;
}

// -------- device scratch (no allocation allowed) --------
__device__ float g_cur1[(size_t)Bsz * Hdim];   // 16 MB

// ============================================================
// gemm1: cur1[b][h] = sum_k x[b][k] * W1[h][k] + b1[h]
// Tile 128x128, BK=16, 256 threads, 8x8 microtile.
// W1 transposed ON THE FLY during B staging (no prep kernel -> ncu's
// first-of-replay capture lands here next round).
//   B staging map: sk=tid&15 (k), sc0=tid>>4 (col), 8 passes of 16 cols.
//     LDG: 16 consecutive k per 16 lanes -> coalesced 64B segments.
//     STS into Bs[16][132] (pad 132): bank=(4*sk+sc)%32 -> 2-way max.
//   A tile stored PRE-DUPLICATED (a,a) in Asd[16][129] float2:
//     staging STS.64 hits 32 distinct banks (conflict-free);
//     inner ap loads are 2-address broadcasts.
//   Inner loop: 8 LDS.64 (ap) + 4 LDS.64 (bp, 128B contiguous, 1 phase)
//               + 32 FFMA2. No MOVs.
// Reduction order: single accumulator per scalar element, ascending-k FMA
// chain; bias added once after full-K reduction (bitwise rel_err 0.0 model).
// ============================================================
__global__ __launch_bounds__(256) void gemm1_kernel(const float* __restrict__ x,
                                                    const float* __restrict__ W1g,
                                                    const float* __restrict__ b1) {
    __shared__ float2 Asd[16][129];   // [k][row] duplicated (a,a)  ~16.5 KB
    __shared__ float  Bs[16][132];    // [k][col], padded            ~8.4 KB
    __shared__ float  b1s[128];

    const int tid = threadIdx.x;
    const int bm = blockIdx.x * 128;

    if (tid < 128) b1s[tid] = b1[tid];

    // A global-load mapping
    const int arow = tid >> 2;          // 0..63
    const int acg  = (tid & 3) * 4;     // k sub-offset 0,4,8,12
    // B global-load mapping (transpose on the fly)
    const int sk  = tid & 15;           // k within tile
    const int sc0 = tid >> 4;           // base col 0..15

    const int tx = tid & 15;            // col group (pairs 2tx+32j)
    const int ty = tid >> 4;            // row group (rows ty*8..ty*8+7)

    // accumulators: 8 rows x 4 column-pairs (cols 2tx+32j, +1)
    u64 cp[8][4];
#pragma unroll
    for (int ri = 0; ri < 8; ri++)
#pragma unroll
        for (int j = 0; j < 4; j++) cp[ri][j] = 0ull;

    // prefetch tile 0
    float4 a0 = *(const float4*)(x + (size_t)(bm + arow) * INF + acg);
    float4 a1 = *(const float4*)(x + (size_t)(bm + arow + 64) * INF + acg);
    float bpre[8];
#pragma unroll
    for (int p = 0; p < 8; p++)
        bpre[p] = W1g[(size_t)(sc0 + 16 * p) * INF + sk];

    const int KITER = INF / 16;  // 49
    for (int t = 0; t < KITER; t++) {
        __syncthreads();
        // stage A (duplicated) and B (transposed) into smem
        Asd[acg + 0][arow] = make_float2(a0.x, a0.x);
        Asd[acg + 1][arow] = make_float2(a0.y, a0.y);
        Asd[acg + 2][arow] = make_float2(a0.z, a0.z);
        Asd[acg + 3][arow] = make_float2(a0.w, a0.w);
        Asd[acg + 0][arow + 64] = make_float2(a1.x, a1.x);
        Asd[acg + 1][arow + 64] = make_float2(a1.y, a1.y);
        Asd[acg + 2][arow + 64] = make_float2(a1.z, a1.z);
        Asd[acg + 3][arow + 64] = make_float2(a1.w, a1.w);
#pragma unroll
        for (int p = 0; p < 8; p++)
            Bs[sk][sc0 + 16 * p] = bpre[p];
        __syncthreads();

        if (t < KITER - 1) {
            int k0 = (t + 1) * 16;
            a0 = *(const float4*)(x + (size_t)(bm + arow) * INF + k0 + acg);
            a1 = *(const float4*)(x + (size_t)(bm + arow + 64) * INF + k0 + acg);
#pragma unroll
            for (int p = 0; p < 8; p++)
                bpre[p] = W1g[(size_t)(sc0 + 16 * p) * INF + k0 + sk];
        }

#pragma unroll
        for (int kk = 0; kk < 16; kk++) {
            u64 ap[8];
#pragma unroll
            for (int ri = 0; ri < 8; ri++)
                ap[ri] = *(const u64*)&Asd[kk][ty * 8 + ri];   // broadcast (a,a)
            u64 bp[4];
#pragma unroll
            for (int j = 0; j < 4; j++)
                bp[j] = *(const u64*)&Bs[kk][2 * tx + 32 * j]; // contiguous pair
#pragma unroll
            for (int ri = 0; ri < 8; ri++)
#pragma unroll
                for (int j = 0; j < 4; j++)
                    cp[ri][j] = fma2(ap[ri], bp[j], cp[ri][j]);
        }
    }

    // epilogue: add b1 (AFTER the full-K reduction), store float2 pairs
#pragma unroll
    for (int ri = 0; ri < 8; ri++) {
        int r = bm + ty * 8 + ri;
        float* orow = g_cur1 + (size_t)r * Hdim;
#pragma unroll
        for (int j = 0; j < 4; j++) {
            int c = 2 * tx + 32 * j;
            float2 v = unpack2(cp[ri][j]);
            float2 s;
            s.x = __fadd_rn(v.x, b1s[c]);
            s.y = __fadd_rn(v.y, b1s[c + 1]);
            *(float2*)&orow[c] = s;
        }
    }
}

// ============================================================
// snn: fused 25-step LIF + tiny GEMM — EXACTLY the R9 known-good version
// (m1 in SHARED memory; the register-array variant spills and costs ~1ms).
// Only change: W2 pairs packed here from gmem (prep kernel removed).
//
// Dynamic smem layout (72.3 KB/block):
//   [0)      cur1s[64][129]
//   [33024)  m1s  [64][129]
//   [66048)  w2s  [128*6] u64
//   [72192)  b2s  [10] float
// ============================================================
#define SNN_CUR1_OFF 0
#define SNN_M1_OFF   33024
#define SNN_W2_OFF   66048
#define SNN_B2_OFF   72192
#define SNN_SMEM_BYTES (72192 + 64)

__global__ __launch_bounds__(64) void snn_kernel(const float* __restrict__ W2g,
                                                 const float* __restrict__ b2g,
                                                 float* __restrict__ out) {
    extern __shared__ char smem[];
    float (*cur1s)[129] = (float (*)[129])(smem + SNN_CUR1_OFF);
    float (*m1s)[129]   = (float (*)[129])(smem + SNN_M1_OFF);
    u64*   w2s          = (u64*)(smem + SNN_W2_OFF);
    float* b2s          = (float*)(smem + SNN_B2_OFF);

    const int tid = threadIdx.x;
    const int rbase = blockIdx.x * 64;

    // load cur1 tile (vector LDG, scalar STS due to pad); zero m1
    for (int i = tid; i < 64 * 32; i += 64) {
        int r = i >> 5;
        int c4 = (i & 31) * 4;
        float4 v = *(const float4*)&g_cur1[(size_t)(rbase + r) * Hdim + c4];
        cur1s[r][c4 + 0] = v.x; cur1s[r][c4 + 1] = v.y;
        cur1s[r][c4 + 2] = v.z; cur1s[r][c4 + 3] = v.w;
    }
    {
        float* m1flat = (float*)(smem + SNN_M1_OFF);
        for (int i = tid; i < 64 * 129; i += 64) m1flat[i] = 0.0f;
    }
    // pack W2 pairs in-kernel (coalesced LDG over h)
#pragma unroll
    for (int hh = 0; hh < 2; hh++) {
        int h = tid + 64 * hh;
#pragma unroll
        for (int p = 0; p < 5; p++)
            w2s[h * 6 + p] = pack2(W2g[(2 * p) * Hdim + h], W2g[(2 * p + 1) * Hdim + h]);
        w2s[h * 6 + 5] = 0ull;
    }
    if (tid < OUTD) b2s[tid] = b2g[tid];
    __syncthreads();

    float m2[OUTD];
#pragma unroll
    for (int o = 0; o < OUTD; o++) m2[o] = 0.0f;

    const int row = rbase + tid;
    const float* myc = cur1s[tid];
    float* mym = m1s[tid];
    float* outp = out + (size_t)row * OUTD;

    const u64 ONE2 = 0x3F8000003F800000ull;  // packed (1.0f, 1.0f)

#pragma unroll 1
    for (int t = 0; t < NSTEP; t++) {
        u64 acc0 = 0ull, acc1 = 0ull, acc2 = 0ull, acc3 = 0ull, acc4 = 0ull;
#pragma unroll 8
        for (int h = 0; h < Hdim; h++) {
            float mo = mym[h];
            // mem = fma(beta, mem, cur1) - r*THR  (XLA's contraction of the reference)
            float m = __fmaf_rn(0.9f, mo, myc[h]);
            if (mo > 1.0f) m = __fadd_rn(m, -1.0f);
            mym[h] = m;
            u64 sp = (m > 1.0f) ? ONE2 : 0ull;   // packed spike (s,s)
            const u64* w = &w2s[h * 6];
            acc0 = fma2(sp, w[0], acc0);
            acc1 = fma2(sp, w[1], acc1);
            acc2 = fma2(sp, w[2], acc2);
            acc3 = fma2(sp, w[3], acc3);
            acc4 = fma2(sp, w[4], acc4);
        }
        float c2[OUTD];
        {
            float2 v;
            v = unpack2(acc0); c2[0] = v.x; c2[1] = v.y;
            v = unpack2(acc1); c2[2] = v.x; c2[3] = v.y;
            v = unpack2(acc2); c2[4] = v.x; c2[5] = v.y;
            v = unpack2(acc3); c2[6] = v.x; c2[7] = v.y;
            v = unpack2(acc4); c2[8] = v.x; c2[9] = v.y;
        }
        float so[OUTD];
#pragma unroll
        for (int o = 0; o < OUTD; o++) {
            float cu = __fadd_rn(c2[o], b2s[o]);        // + b2 after the reduction
            float mo = m2[o];
            float m = __fmaf_rn(0.9f, mo, cu);          // one rounding (FFMA)
            if (mo > 1.0f) m = __fadd_rn(m, -1.0f);
            m2[o] = m;
            so[o] = (m > 1.0f) ? 1.0f : 0.0f;
        }
        float* op = outp + (size_t)t * Bsz * OUTD;
#pragma unroll
        for (int p = 0; p < 5; p++)
            *(float2*)(op + 2 * p) = make_float2(so[2 * p], so[2 * p + 1]);
    }
}

// ============================================================
extern "C" void kernel_launch(void* const* d_in, const int* in_sizes, int n_in,
                              void* d_out, int out_size) {
    (void)in_sizes; (void)n_in; (void)out_size;
    const float* x  = (const float*)d_in[0];
    const float* W1 = (const float*)d_in[1];
    const float* b1 = (const float*)d_in[2];
    const float* W2 = (const float*)d_in[3];
    const float* b2 = (const float*)d_in[4];
    float* out = (float*)d_out;

    static bool attr_set = false;
    if (!attr_set) {
        cudaFuncSetAttribute(snn_kernel, cudaFuncAttributeMaxDynamicSharedMemorySize,
                             SNN_SMEM_BYTES);
        attr_set = true;
    }

    gemm1_kernel<<<Bsz / 128, 256>>>(x, W1, b1);
    snn_kernel<<<Bsz / 64, 64, SNN_SMEM_BYTES>>>(W2, b2, out);
}